// round 2
// baseline (speedup 1.0000x reference)
#include <cuda_runtime.h>
#include <cuda_bf16.h>

#define DIM   512
#define HEADS 16
#define HD    32
#define SS    49
#define BTOT  2048
#define MROWS (BTOT * SS)   // 100352 = 784 * 128

// Scratch (allocation-free rule: __device__ globals)
__device__ float g_qkv[(size_t)MROWS * 3 * DIM];   // 616 MB
__device__ float g_att[(size_t)MROWS * DIM];       // 205 MB

// ---------------------------------------------------------------------------
// SGEMM: C[M,N] = A[M,K] @ B[K,N] + bias[N]
// BM=BN=128, BK=8, 256 threads, 8x8 per-thread microtile.
// Requires M%128==0, N%128==0, K%8==0 (holds for both GEMMs here).
// ---------------------------------------------------------------------------
__global__ __launch_bounds__(256) void sgemm_bias_kernel(
    const float* __restrict__ A, const float* __restrict__ B,
    const float* __restrict__ bias, float* __restrict__ C,
    int M, int N, int K)
{
    const int BM = 128, BN = 128, BK = 8, TM = 8, TN = 8;
    __shared__ float As[BK][BM];   // A stored transposed
    __shared__ float Bs[BK][BN];

    const int tid = threadIdx.x;
    const int tx = tid & 15;        // 0..15 -> col microtile
    const int ty = tid >> 4;        // 0..15 -> row microtile

    const long crow = (long)blockIdx.y * BM;
    const long ccol = (long)blockIdx.x * BN;

    const int aRow = tid >> 1;          // 0..127
    const int aCol = (tid & 1) * 4;     // 0 or 4
    const int bRow = tid >> 5;          // 0..7
    const int bCol = (tid & 31) * 4;    // 0..124

    const float* Aptr = A + (crow + aRow) * (long)K + aCol;
    const float* Bptr = B + (long)bRow * N + ccol + bCol;

    float acc[TM][TN];
    #pragma unroll
    for (int i = 0; i < TM; i++)
        #pragma unroll
        for (int j = 0; j < TN; j++) acc[i][j] = 0.f;

    for (int k0 = 0; k0 < K; k0 += BK) {
        float4 a4 = *reinterpret_cast<const float4*>(Aptr);
        As[aCol + 0][aRow] = a4.x;
        As[aCol + 1][aRow] = a4.y;
        As[aCol + 2][aRow] = a4.z;
        As[aCol + 3][aRow] = a4.w;
        *reinterpret_cast<float4*>(&Bs[bRow][bCol]) =
            *reinterpret_cast<const float4*>(Bptr);
        __syncthreads();

        #pragma unroll
        for (int kk = 0; kk < BK; kk++) {
            float ra[TM], rb[TN];
            float4 t;
            t = *reinterpret_cast<const float4*>(&As[kk][ty * TM]);
            ra[0] = t.x; ra[1] = t.y; ra[2] = t.z; ra[3] = t.w;
            t = *reinterpret_cast<const float4*>(&As[kk][ty * TM + 4]);
            ra[4] = t.x; ra[5] = t.y; ra[6] = t.z; ra[7] = t.w;
            t = *reinterpret_cast<const float4*>(&Bs[kk][tx * TN]);
            rb[0] = t.x; rb[1] = t.y; rb[2] = t.z; rb[3] = t.w;
            t = *reinterpret_cast<const float4*>(&Bs[kk][tx * TN + 4]);
            rb[4] = t.x; rb[5] = t.y; rb[6] = t.z; rb[7] = t.w;
            #pragma unroll
            for (int i = 0; i < TM; i++)
                #pragma unroll
                for (int j = 0; j < TN; j++)
                    acc[i][j] += ra[i] * rb[j];
        }
        __syncthreads();
        Aptr += BK;
        Bptr += (long)BK * N;
    }

    // Epilogue: add bias, vectorized store
    #pragma unroll
    for (int i = 0; i < TM; i++) {
        long r = crow + ty * TM + i;
        #pragma unroll
        for (int j = 0; j < TN; j += 4) {
            long c = ccol + tx * TN + j;
            float4 o;
            o.x = acc[i][j + 0] + bias[c + 0];
            o.y = acc[i][j + 1] + bias[c + 1];
            o.z = acc[i][j + 2] + bias[c + 2];
            o.w = acc[i][j + 3] + bias[c + 3];
            *reinterpret_cast<float4*>(&C[r * N + c]) = o;
        }
    }
}

// ---------------------------------------------------------------------------
// Fused window attention: one block per (window b, head h).
// qkv layout: row (b*49+s), 1536 cols = [3][16][32]
// out layout: [b*49+s][h*32+d]  (head-interleaved, ready for proj GEMM)
// ---------------------------------------------------------------------------
__global__ __launch_bounds__(256) void attn_kernel(
    const float* __restrict__ qkv, const float* __restrict__ mask,
    const float* __restrict__ bias_table, const int* __restrict__ rel_idx,
    float* __restrict__ out)
{
    const int b = blockIdx.x;
    const int h = blockIdx.y;
    const int tid = threadIdx.x;

    __shared__ float q[SS][HD + 1];
    __shared__ float k[SS][HD + 1];
    __shared__ float v[SS][HD + 1];
    __shared__ float at[SS][SS];

    const float scale = 0.17677669529663687f;  // 1/sqrt(32)
    const float* base = qkv + (long)b * SS * (3 * DIM) + h * HD;

    for (int e = tid; e < SS * HD; e += 256) {
        int s = e >> 5, d = e & 31;
        const float* row = base + (long)s * (3 * DIM) + d;
        q[s][d] = row[0] * scale;
        k[s][d] = row[DIM];
        v[s][d] = row[2 * DIM];
    }
    __syncthreads();

    // attn = q @ k^T + bias + mask
    const float* mrow = mask + (long)(b & 3) * SS * SS;
    for (int e = tid; e < SS * SS; e += 256) {
        int qi = e / SS, ki = e - qi * SS;
        float sum = 0.f;
        #pragma unroll
        for (int d = 0; d < HD; d++) sum += q[qi][d] * k[ki][d];
        sum += bias_table[rel_idx[e] * HEADS + h] + mrow[e];
        at[qi][ki] = sum;
    }
    __syncthreads();

    // Row softmax (one thread per row)
    if (tid < SS) {
        float m = -1e30f;
        #pragma unroll
        for (int j = 0; j < SS; j++) m = fmaxf(m, at[tid][j]);
        float sum = 0.f;
        #pragma unroll
        for (int j = 0; j < SS; j++) {
            float e2 = __expf(at[tid][j] - m);
            at[tid][j] = e2;
            sum += e2;
        }
        float inv = 1.0f / sum;
        #pragma unroll
        for (int j = 0; j < SS; j++) at[tid][j] *= inv;
    }
    __syncthreads();

    // out = attn @ v
    for (int e = tid; e < SS * HD; e += 256) {
        int qi = e >> 5, d = e & 31;
        float sum = 0.f;
        #pragma unroll
        for (int j = 0; j < SS; j++) sum += at[qi][j] * v[j][d];
        out[((long)b * SS + qi) * DIM + h * HD + d] = sum;
    }
}

// ---------------------------------------------------------------------------
extern "C" void kernel_launch(void* const* d_in, const int* in_sizes, int n_in,
                              void* d_out, int out_size)
{
    const float* x          = (const float*)d_in[0];   // [2048,49,512]
    const float* mask       = (const float*)d_in[1];   // [4,49,49]
    const float* w_qkv      = (const float*)d_in[2];   // [512,1536]
    const float* b_qkv      = (const float*)d_in[3];   // [1536]
    const float* w_proj     = (const float*)d_in[4];   // [512,512]
    const float* b_proj     = (const float*)d_in[5];   // [512]
    const float* bias_table = (const float*)d_in[6];   // [169,16]
    const int*   rel_idx    = (const int*)d_in[7];     // [49,49]
    float* out = (float*)d_out;

    float* qkv_buf = nullptr;
    float* att_buf = nullptr;
    cudaGetSymbolAddress((void**)&qkv_buf, g_qkv);
    cudaGetSymbolAddress((void**)&att_buf, g_att);

    // 1) QKV GEMM: [100352,512] @ [512,1536] + b_qkv
    {
        dim3 grid(3 * DIM / 128, MROWS / 128);   // (12, 784)
        sgemm_bias_kernel<<<grid, 256>>>(x, w_qkv, b_qkv, qkv_buf,
                                         MROWS, 3 * DIM, DIM);
    }

    // 2) Window attention, one block per (window, head)
    {
        dim3 grid(BTOT, HEADS);
        attn_kernel<<<grid, 256>>>(qkv_buf, mask, bias_table, rel_idx, att_buf);
    }

    // 3) Proj GEMM: [100352,512] @ [512,512] + b_proj
    {
        dim3 grid(DIM / 128, MROWS / 128);       // (4, 784)
        sgemm_bias_kernel<<<grid, 256>>>(att_buf, w_proj, b_proj, out,
                                         MROWS, DIM, DIM);
    }
}

// round 4
// speedup vs baseline: 1.8334x; 1.8334x over previous
#include <cuda_runtime.h>
#include <cuda_bf16.h>
#include <cstdint>

#define DIM   512
#define HEADS 16
#define HD    32
#define SS    49
#define BTOT  2048
#define MROWS (BTOT * SS)   // 100352 = 784 * 128
#define KDIM  512

// ---------------- scratch (__device__ globals; allocation-free rule) -------
__device__ __nv_bfloat16 g_xh[(size_t)MROWS * KDIM];
__device__ __nv_bfloat16 g_xl[(size_t)MROWS * KDIM];
__device__ float         g_qkv[(size_t)MROWS * 3 * DIM];
__device__ __nv_bfloat16 g_ah[(size_t)MROWS * DIM];
__device__ __nv_bfloat16 g_al[(size_t)MROWS * DIM];
__device__ __nv_bfloat16 g_wqh[(size_t)3 * DIM * KDIM];   // transposed [1536][512]
__device__ __nv_bfloat16 g_wql[(size_t)3 * DIM * KDIM];
__device__ __nv_bfloat16 g_wph[(size_t)DIM * KDIM];       // transposed [512][512]
__device__ __nv_bfloat16 g_wpl[(size_t)DIM * KDIM];

// ---------------- PTX helpers (baseline PTX only, no tcgen05) --------------
__device__ __forceinline__ uint32_t smem_u32(const void* p) {
    uint32_t a;
    asm("{ .reg .u64 t; cvta.to.shared.u64 t, %1; cvt.u32.u64 %0, t; }"
        : "=r"(a) : "l"(p));
    return a;
}
__device__ __forceinline__ void cpa16(uint32_t s, const void* g) {
    asm volatile("cp.async.cg.shared.global [%0], [%1], 16;" :: "r"(s), "l"(g));
}
#define CP_COMMIT() asm volatile("cp.async.commit_group;")
#define CP_WAIT1()  asm volatile("cp.async.wait_group 1;")

#define LDSM4(r, addr) \
    asm volatile("ldmatrix.sync.aligned.m8n8.x4.shared.b16 {%0,%1,%2,%3}, [%4];" \
        : "=r"((r)[0]), "=r"((r)[1]), "=r"((r)[2]), "=r"((r)[3]) : "r"(addr))

#define MMA16816(d, a, b0, b1) \
    asm volatile("mma.sync.aligned.m16n8k16.row.col.f32.bf16.bf16.f32 " \
        "{%0,%1,%2,%3}, {%4,%5,%6,%7}, {%8,%9}, {%0,%1,%2,%3};" \
        : "+f"((d)[0]), "+f"((d)[1]), "+f"((d)[2]), "+f"((d)[3]) \
        : "r"((a)[0]), "r"((a)[1]), "r"((a)[2]), "r"((a)[3]), "r"(b0), "r"(b1))

// ---------------------------------------------------------------------------
// Split-precision HMMA GEMM: C[M,N] = (Ah+Al)[M,512] @ (Bh+Bl)^T + bias
// A*: [M][512] bf16 row-major. B*: [N][512] bf16 row-major (i.e. W^T).
// Tile 128x128, BK=32, 3-stage cp.async pipeline, 8 warps (64x32 each).
// ---------------------------------------------------------------------------
#define TSTRIDE     80                       // bytes/row: 64B data + 16B pad
#define TILE_BYTES  (128 * TSTRIDE)          // 10240
#define STAGE_BYTES (4 * TILE_BYTES)         // 40960 (Ah,Al,Bh,Bl)
#define GEMM_SMEM   (3 * STAGE_BYTES)        // 122880

__global__ __launch_bounds__(256, 1) void gemm_bf16x3_mma(
    const __nv_bfloat16* __restrict__ Ah, const __nv_bfloat16* __restrict__ Al,
    const __nv_bfloat16* __restrict__ Bh, const __nv_bfloat16* __restrict__ Bl,
    const float* __restrict__ bias, float* __restrict__ C, int N)
{
    extern __shared__ char smem[];
    const uint32_t sb = smem_u32(smem);
    const int tid  = threadIdx.x;
    const int lane = tid & 31, wid = tid >> 5;
    const int wr = wid >> 2, wc = wid & 3;        // warp grid 2x4
    const long m0 = (long)blockIdx.y * 128;
    const int  n0 = blockIdx.x * 128;

    // ---- stage loader: 4 tiles x 512 16B-chunks, 2 chunks per thread/tile
    auto load_stage = [&](int s, int k0) {
        const uint32_t base = sb + (uint32_t)s * STAGE_BYTES;
        #pragma unroll
        for (int half = 0; half < 2; half++) {
            const int chunk = tid + half * 256;
            const int r = chunk >> 2, c = chunk & 3;
            const uint32_t off = (uint32_t)r * TSTRIDE + c * 16;
            const long aIdx = (m0 + r) * (long)KDIM + k0;
            const long bIdx = ((long)n0 + r) * (long)KDIM + k0;
            cpa16(base + off,                  (const char*)(Ah + aIdx) + c * 16);
            cpa16(base + TILE_BYTES + off,     (const char*)(Al + aIdx) + c * 16);
            cpa16(base + 2 * TILE_BYTES + off, (const char*)(Bh + bIdx) + c * 16);
            cpa16(base + 3 * TILE_BYTES + off, (const char*)(Bl + bIdx) + c * 16);
        }
    };

    float acc[4][4][4];
    #pragma unroll
    for (int mi = 0; mi < 4; mi++)
        #pragma unroll
        for (int ni = 0; ni < 4; ni++)
            #pragma unroll
            for (int j = 0; j < 4; j++) acc[mi][ni][j] = 0.f;

    // per-lane ldmatrix base offsets (within a stage, kk=0)
    const uint32_t aRowOff =
        (uint32_t)(wr * 64 + (lane & 15)) * TSTRIDE + (lane >> 4) * 16;
    const int bg = lane >> 3, bfr = bg >> 1, bkh = bg & 1;
    const uint32_t bRowOff0 =
        2 * TILE_BYTES + (uint32_t)(wc * 32 + bfr * 8 + (lane & 7)) * TSTRIDE + bkh * 16;

    auto compute_stage = [&](int s) {
        const uint32_t base = sb + (uint32_t)s * STAGE_BYTES;
        #pragma unroll
        for (int kk = 0; kk < 2; kk++) {
            uint32_t ah[4][4], al[4][4], bh[2][4], bl[2][4];
            #pragma unroll
            for (int mi = 0; mi < 4; mi++) {
                uint32_t addr = base + aRowOff + (uint32_t)mi * 16 * TSTRIDE + kk * 32;
                LDSM4(ah[mi], addr);
                LDSM4(al[mi], addr + TILE_BYTES);
            }
            #pragma unroll
            for (int p = 0; p < 2; p++) {
                uint32_t addr = base + bRowOff0 + (uint32_t)p * 16 * TSTRIDE + kk * 32;
                LDSM4(bh[p], addr);
                LDSM4(bl[p], addr + TILE_BYTES);
            }
            #pragma unroll
            for (int mi = 0; mi < 4; mi++)
                #pragma unroll
                for (int ni = 0; ni < 4; ni++) {
                    const int p = ni >> 1, rb = (ni & 1) * 2;
                    MMA16816(acc[mi][ni], ah[mi], bh[p][rb], bh[p][rb + 1]);
                    MMA16816(acc[mi][ni], ah[mi], bl[p][rb], bl[p][rb + 1]);
                    MMA16816(acc[mi][ni], al[mi], bh[p][rb], bh[p][rb + 1]);
                }
        }
    };

    // ---- 3-stage pipeline over 16 K-iterations (K=512, BK=32)
    load_stage(0, 0);  CP_COMMIT();
    load_stage(1, 32); CP_COMMIT();
    #pragma unroll 1
    for (int kt = 0; kt < 16; kt++) {
        CP_WAIT1();
        __syncthreads();
        if (kt + 2 < 16) load_stage((kt + 2) % 3, (kt + 2) * 32);
        CP_COMMIT();
        compute_stage(kt % 3);
    }

    // ---- epilogue: registers -> gmem with bias
    const int r0 = lane >> 2, cpos = (lane & 3) * 2;
    #pragma unroll
    for (int ni = 0; ni < 4; ni++) {
        const int col = n0 + wc * 32 + ni * 8 + cpos;
        const float bx = bias[col], by = bias[col + 1];
        #pragma unroll
        for (int mi = 0; mi < 4; mi++) {
            const long row = m0 + wr * 64 + mi * 16 + r0;
            float2 v0 = {acc[mi][ni][0] + bx, acc[mi][ni][1] + by};
            float2 v1 = {acc[mi][ni][2] + bx, acc[mi][ni][3] + by};
            *(float2*)&C[row * (long)N + col]       = v0;
            *(float2*)&C[(row + 8) * (long)N + col] = v1;
        }
    }
}

// ---------------------------------------------------------------------------
// fp32 -> (hi, lo) bf16 split, vectorized
// ---------------------------------------------------------------------------
__global__ void split_kernel(const float* __restrict__ in,
                             __nv_bfloat16* __restrict__ hi,
                             __nv_bfloat16* __restrict__ lo, long n4)
{
    long i = (long)blockIdx.x * blockDim.x + threadIdx.x;
    const long stride = (long)gridDim.x * blockDim.x;
    for (; i < n4; i += stride) {
        float4 v = ((const float4*)in)[i];
        __nv_bfloat16 h0 = __float2bfloat16(v.x);
        __nv_bfloat16 h1 = __float2bfloat16(v.y);
        __nv_bfloat16 h2 = __float2bfloat16(v.z);
        __nv_bfloat16 h3 = __float2bfloat16(v.w);
        __nv_bfloat162* hp = (__nv_bfloat162*)hi + 2 * i;
        hp[0] = __nv_bfloat162(h0, h1);
        hp[1] = __nv_bfloat162(h2, h3);
        __nv_bfloat162* lp = (__nv_bfloat162*)lo + 2 * i;
        lp[0] = __nv_bfloat162(__float2bfloat16(v.x - __bfloat162float(h0)),
                               __float2bfloat16(v.y - __bfloat162float(h1)));
        lp[1] = __nv_bfloat162(__float2bfloat16(v.z - __bfloat162float(h2)),
                               __float2bfloat16(v.w - __bfloat162float(h3)));
    }
}

// Transpose + split weights: out[n][k] = split(w[k][n]); K=512 fixed
__global__ void wsplit_kernel(const float* __restrict__ w,
                              __nv_bfloat16* __restrict__ hi,
                              __nv_bfloat16* __restrict__ lo, int N, int total)
{
    int i = blockIdx.x * 256 + threadIdx.x;
    if (i >= total) return;
    int k = i & (KDIM - 1);
    int n = i >> 9;
    float v = w[(long)k * N + n];
    __nv_bfloat16 h = __float2bfloat16(v);
    hi[i] = h;
    lo[i] = __float2bfloat16(v - __bfloat162float(h));
}

// ---------------------------------------------------------------------------
// Fused window attention (fp32), writes split bf16 output for proj GEMM
// ---------------------------------------------------------------------------
__global__ __launch_bounds__(256) void attn_kernel(
    const float* __restrict__ qkv, const float* __restrict__ mask,
    const float* __restrict__ bias_table, const int* __restrict__ rel_idx,
    __nv_bfloat16* __restrict__ out_hi, __nv_bfloat16* __restrict__ out_lo)
{
    const int b = blockIdx.x;
    const int h = blockIdx.y;
    const int tid = threadIdx.x;

    __shared__ float q[SS][HD + 1];
    __shared__ float k[SS][HD + 1];
    __shared__ float v[SS][HD + 1];
    __shared__ float at[SS][SS];

    const float scale = 0.17677669529663687f;  // 1/sqrt(32)
    const float* base = qkv + (long)b * SS * (3 * DIM) + h * HD;

    for (int e = tid; e < SS * HD; e += 256) {
        int s = e >> 5, d = e & 31;
        const float* row = base + (long)s * (3 * DIM) + d;
        q[s][d] = row[0] * scale;
        k[s][d] = row[DIM];
        v[s][d] = row[2 * DIM];
    }
    __syncthreads();

    const float* mrow = mask + (long)(b & 3) * SS * SS;
    for (int e = tid; e < SS * SS; e += 256) {
        int qi = e / SS, ki = e - qi * SS;
        float sum = 0.f;
        #pragma unroll
        for (int d = 0; d < HD; d++) sum += q[qi][d] * k[ki][d];
        sum += bias_table[rel_idx[e] * HEADS + h] + mrow[e];
        at[qi][ki] = sum;
    }
    __syncthreads();

    if (tid < SS) {
        float m = -1e30f;
        #pragma unroll
        for (int j = 0; j < SS; j++) m = fmaxf(m, at[tid][j]);
        float sum = 0.f;
        #pragma unroll
        for (int j = 0; j < SS; j++) {
            float e2 = __expf(at[tid][j] - m);
            at[tid][j] = e2;
            sum += e2;
        }
        float inv = 1.0f / sum;
        #pragma unroll
        for (int j = 0; j < SS; j++) at[tid][j] *= inv;
    }
    __syncthreads();

    for (int e = tid; e < SS * HD; e += 256) {
        int qi = e >> 5, d = e & 31;
        float sum = 0.f;
        #pragma unroll
        for (int j = 0; j < SS; j++) sum += at[qi][j] * v[j][d];
        long idx = ((long)b * SS + qi) * DIM + h * HD + d;
        __nv_bfloat16 hbf = __float2bfloat16(sum);
        out_hi[idx] = hbf;
        out_lo[idx] = __float2bfloat16(sum - __bfloat162float(hbf));
    }
}

// ---------------------------------------------------------------------------
extern "C" void kernel_launch(void* const* d_in, const int* in_sizes, int n_in,
                              void* d_out, int out_size)
{
    const float* x          = (const float*)d_in[0];
    const float* mask       = (const float*)d_in[1];
    const float* w_qkv      = (const float*)d_in[2];
    const float* b_qkv      = (const float*)d_in[3];
    const float* w_proj     = (const float*)d_in[4];
    const float* b_proj     = (const float*)d_in[5];
    const float* bias_table = (const float*)d_in[6];
    const int*   rel_idx    = (const int*)d_in[7];
    float* out = (float*)d_out;

    __nv_bfloat16 *xh, *xl, *ah, *al, *wqh, *wql, *wph, *wpl;
    float* qkv;
    cudaGetSymbolAddress((void**)&xh,  g_xh);
    cudaGetSymbolAddress((void**)&xl,  g_xl);
    cudaGetSymbolAddress((void**)&qkv, g_qkv);
    cudaGetSymbolAddress((void**)&ah,  g_ah);
    cudaGetSymbolAddress((void**)&al,  g_al);
    cudaGetSymbolAddress((void**)&wqh, g_wqh);
    cudaGetSymbolAddress((void**)&wql, g_wql);
    cudaGetSymbolAddress((void**)&wph, g_wph);
    cudaGetSymbolAddress((void**)&wpl, g_wpl);

    cudaFuncSetAttribute(gemm_bf16x3_mma,
                         cudaFuncAttributeMaxDynamicSharedMemorySize, GEMM_SMEM);

    // 1) splits
    {
        long n4 = (long)MROWS * KDIM / 4;
        split_kernel<<<2048, 256>>>(x, xh, xl, n4);
        wsplit_kernel<<<(3 * DIM * KDIM) / 256, 256>>>(w_qkv, wqh, wql, 3 * DIM,
                                                       3 * DIM * KDIM);
        wsplit_kernel<<<(DIM * KDIM) / 256, 256>>>(w_proj, wph, wpl, DIM, DIM * KDIM);
    }

    // 2) QKV GEMM: [100352,512] @ [512,1536] + b_qkv  (HMMA bf16x3)
    {
        dim3 grid(12, 784);
        gemm_bf16x3_mma<<<grid, 256, GEMM_SMEM>>>(xh, xl, wqh, wql, b_qkv, qkv,
                                                  3 * DIM);
    }

    // 3) window attention (emits split bf16)
    {
        dim3 grid(BTOT, HEADS);
        attn_kernel<<<grid, 256>>>(qkv, mask, bias_table, rel_idx, ah, al);
    }

    // 4) Proj GEMM: [100352,512] @ [512,512] + b_proj
    {
        dim3 grid(4, 784);
        gemm_bf16x3_mma<<<grid, 256, GEMM_SMEM>>>(ah, al, wph, wpl, b_proj, out,
                                                  DIM);
    }
}

// round 5
// speedup vs baseline: 2.4037x; 1.3110x over previous
#include <cuda_runtime.h>
#include <cuda_bf16.h>
#include <cstdint>

#define DIM   512
#define HEADS 16
#define HD    32
#define SS    49
#define BTOT  2048
#define MROWS (BTOT * SS)   // 100352 = 784 * 128
#define KDIM  512

// ---------------- scratch (__device__ globals; allocation-free rule) -------
__device__ __nv_bfloat16 g_xh[(size_t)MROWS * KDIM];
__device__ __nv_bfloat16 g_xl[(size_t)MROWS * KDIM];
__device__ float         g_qkv[(size_t)MROWS * 3 * DIM];
__device__ __nv_bfloat16 g_ah[(size_t)MROWS * DIM];
__device__ __nv_bfloat16 g_al[(size_t)MROWS * DIM];
__device__ __nv_bfloat16 g_wqh[(size_t)3 * DIM * KDIM];   // transposed [1536][512]
__device__ __nv_bfloat16 g_wql[(size_t)3 * DIM * KDIM];
__device__ __nv_bfloat16 g_wph[(size_t)DIM * KDIM];       // transposed [512][512]
__device__ __nv_bfloat16 g_wpl[(size_t)DIM * KDIM];
__device__ float         g_bm[4 * HEADS * SS * SS];       // bias+mask table

// ---------------- PTX helpers ---------------------------------------------
__device__ __forceinline__ uint32_t smem_u32(const void* p) {
    uint32_t a;
    asm("{ .reg .u64 t; cvta.to.shared.u64 t, %1; cvt.u32.u64 %0, t; }"
        : "=r"(a) : "l"(p));
    return a;
}
__device__ __forceinline__ void cpa16(uint32_t s, const void* g) {
    asm volatile("cp.async.cg.shared.global [%0], [%1], 16;" :: "r"(s), "l"(g));
}
#define CP_COMMIT() asm volatile("cp.async.commit_group;")
#define CP_WAIT1()  asm volatile("cp.async.wait_group 1;")

#define LDSM4(r, addr) \
    asm volatile("ldmatrix.sync.aligned.m8n8.x4.shared.b16 {%0,%1,%2,%3}, [%4];" \
        : "=r"((r)[0]), "=r"((r)[1]), "=r"((r)[2]), "=r"((r)[3]) : "r"(addr))

#define MMA16816(d, a, b0, b1) \
    asm volatile("mma.sync.aligned.m16n8k16.row.col.f32.bf16.bf16.f32 " \
        "{%0,%1,%2,%3}, {%4,%5,%6,%7}, {%8,%9}, {%0,%1,%2,%3};" \
        : "+f"((d)[0]), "+f"((d)[1]), "+f"((d)[2]), "+f"((d)[3]) \
        : "r"((a)[0]), "r"((a)[1]), "r"((a)[2]), "r"((a)[3]), "r"(b0), "r"(b1))

// ---------------------------------------------------------------------------
// Split-precision HMMA GEMM: C[M,N] = (Ah+Al)[M,512] @ (Bh+Bl)^T + bias
// Tile 128x128, BK=32, 2-stage cp.async pipeline, 8 warps, 2 CTAs/SM target.
// ---------------------------------------------------------------------------
#define TSTRIDE     80                       // bytes/row: 64B data + 16B pad
#define TILE_BYTES  (128 * TSTRIDE)          // 10240
#define STAGE_BYTES (4 * TILE_BYTES)         // 40960 (Ah,Al,Bh,Bl)
#define GEMM_SMEM   (2 * STAGE_BYTES)        // 81920

__global__ __launch_bounds__(256, 2) void gemm_bf16x3_mma(
    const __nv_bfloat16* __restrict__ Ah, const __nv_bfloat16* __restrict__ Al,
    const __nv_bfloat16* __restrict__ Bh, const __nv_bfloat16* __restrict__ Bl,
    const float* __restrict__ bias, float* __restrict__ C, int N)
{
    extern __shared__ char smem[];
    const uint32_t sb = smem_u32(smem);
    const int tid  = threadIdx.x;
    const int lane = tid & 31, wid = tid >> 5;
    const int wr = wid >> 2, wc = wid & 3;        // warp grid 2x4
    const long m0 = (long)blockIdx.y * 128;
    const int  n0 = blockIdx.x * 128;

    auto load_stage = [&](int s, int k0) {
        const uint32_t base = sb + (uint32_t)s * STAGE_BYTES;
        #pragma unroll
        for (int half = 0; half < 2; half++) {
            const int chunk = tid + half * 256;
            const int r = chunk >> 2, c = chunk & 3;
            const uint32_t off = (uint32_t)r * TSTRIDE + c * 16;
            const long aIdx = (m0 + r) * (long)KDIM + k0;
            const long bIdx = ((long)n0 + r) * (long)KDIM + k0;
            cpa16(base + off,                  (const char*)(Ah + aIdx) + c * 16);
            cpa16(base + TILE_BYTES + off,     (const char*)(Al + aIdx) + c * 16);
            cpa16(base + 2 * TILE_BYTES + off, (const char*)(Bh + bIdx) + c * 16);
            cpa16(base + 3 * TILE_BYTES + off, (const char*)(Bl + bIdx) + c * 16);
        }
    };

    float acc[4][4][4];
    #pragma unroll
    for (int mi = 0; mi < 4; mi++)
        #pragma unroll
        for (int ni = 0; ni < 4; ni++)
            #pragma unroll
            for (int j = 0; j < 4; j++) acc[mi][ni][j] = 0.f;

    const uint32_t aRowOff =
        (uint32_t)(wr * 64 + (lane & 15)) * TSTRIDE + (lane >> 4) * 16;
    const int bg = lane >> 3, bfr = bg >> 1, bkh = bg & 1;
    const uint32_t bRowOff0 =
        2 * TILE_BYTES + (uint32_t)(wc * 32 + bfr * 8 + (lane & 7)) * TSTRIDE + bkh * 16;

    auto compute_stage = [&](int s) {
        const uint32_t base = sb + (uint32_t)s * STAGE_BYTES;
        #pragma unroll
        for (int kk = 0; kk < 2; kk++) {
            uint32_t ah[4][4], al[4][4];
            #pragma unroll
            for (int mi = 0; mi < 4; mi++) {
                uint32_t addr = base + aRowOff + (uint32_t)mi * 16 * TSTRIDE + kk * 32;
                LDSM4(ah[mi], addr);
                LDSM4(al[mi], addr + TILE_BYTES);
            }
            #pragma unroll
            for (int p = 0; p < 2; p++) {    // B frags loaded per-p: short live range
                uint32_t bh[4], bl[4];
                uint32_t addr = base + bRowOff0 + (uint32_t)p * 16 * TSTRIDE + kk * 32;
                LDSM4(bh, addr);
                LDSM4(bl, addr + TILE_BYTES);
                #pragma unroll
                for (int mi = 0; mi < 4; mi++)
                    #pragma unroll
                    for (int q2 = 0; q2 < 2; q2++) {
                        const int ni = p * 2 + q2, rb = q2 * 2;
                        MMA16816(acc[mi][ni], ah[mi], bh[rb], bh[rb + 1]);
                        MMA16816(acc[mi][ni], ah[mi], bl[rb], bl[rb + 1]);
                        MMA16816(acc[mi][ni], al[mi], bh[rb], bh[rb + 1]);
                    }
            }
        }
    };

    // ---- 2-stage pipeline over 16 K-iterations (K=512, BK=32)
    load_stage(0, 0);  CP_COMMIT();
    load_stage(1, 32); CP_COMMIT();
    #pragma unroll 1
    for (int kt = 0; kt < 16; kt++) {
        CP_WAIT1();
        __syncthreads();
        compute_stage(kt & 1);
        __syncthreads();
        if (kt + 2 < 16) {
            load_stage(kt & 1, (kt + 2) * 32);
            CP_COMMIT();
        }
    }

    // ---- epilogue
    const int r0 = lane >> 2, cpos = (lane & 3) * 2;
    #pragma unroll
    for (int ni = 0; ni < 4; ni++) {
        const int col = n0 + wc * 32 + ni * 8 + cpos;
        const float bx = bias[col], by = bias[col + 1];
        #pragma unroll
        for (int mi = 0; mi < 4; mi++) {
            const long row = m0 + wr * 64 + mi * 16 + r0;
            float2 v0 = {acc[mi][ni][0] + bx, acc[mi][ni][1] + by};
            float2 v1 = {acc[mi][ni][2] + bx, acc[mi][ni][3] + by};
            *(float2*)&C[row * (long)N + col]       = v0;
            *(float2*)&C[(row + 8) * (long)N + col] = v1;
        }
    }
}

// ---------------------------------------------------------------------------
// fp32 -> (hi, lo) bf16 split
// ---------------------------------------------------------------------------
__global__ void split_kernel(const float* __restrict__ in,
                             __nv_bfloat16* __restrict__ hi,
                             __nv_bfloat16* __restrict__ lo, long n4)
{
    long i = (long)blockIdx.x * blockDim.x + threadIdx.x;
    const long stride = (long)gridDim.x * blockDim.x;
    for (; i < n4; i += stride) {
        float4 v = ((const float4*)in)[i];
        __nv_bfloat16 h0 = __float2bfloat16(v.x);
        __nv_bfloat16 h1 = __float2bfloat16(v.y);
        __nv_bfloat16 h2 = __float2bfloat16(v.z);
        __nv_bfloat16 h3 = __float2bfloat16(v.w);
        __nv_bfloat162* hp = (__nv_bfloat162*)hi + 2 * i;
        hp[0] = __nv_bfloat162(h0, h1);
        hp[1] = __nv_bfloat162(h2, h3);
        __nv_bfloat162* lp = (__nv_bfloat162*)lo + 2 * i;
        lp[0] = __nv_bfloat162(__float2bfloat16(v.x - __bfloat162float(h0)),
                               __float2bfloat16(v.y - __bfloat162float(h1)));
        lp[1] = __nv_bfloat162(__float2bfloat16(v.z - __bfloat162float(h2)),
                               __float2bfloat16(v.w - __bfloat162float(h3)));
    }
}

__global__ void wsplit_kernel(const float* __restrict__ w,
                              __nv_bfloat16* __restrict__ hi,
                              __nv_bfloat16* __restrict__ lo, int N, int total)
{
    int i = blockIdx.x * 256 + threadIdx.x;
    if (i >= total) return;
    int k = i & (KDIM - 1);
    int n = i >> 9;
    float v = w[(long)k * N + n];
    __nv_bfloat16 h = __float2bfloat16(v);
    hi[i] = h;
    lo[i] = __float2bfloat16(v - __bfloat162float(h));
}

// bias+mask precompute: bm[w][h][q*49+k] = bias_table[rel_idx]*+mask
__global__ void biasmask_kernel(const float* __restrict__ bias_table,
                                const int* __restrict__ rel_idx,
                                const float* __restrict__ mask,
                                float* __restrict__ bm)
{
    int idx = blockIdx.x * 256 + threadIdx.x;
    const int total = 4 * HEADS * SS * SS;
    if (idx >= total) return;
    int e = idx % (SS * SS);
    int h = (idx / (SS * SS)) % HEADS;
    int w = idx / (SS * SS * HEADS);
    bm[idx] = bias_table[rel_idx[e] * HEADS + h] + mask[w * SS * SS + e];
}

// ---------------------------------------------------------------------------
// Window attention, register-tiled. Block = (window, head), 128 threads.
// ---------------------------------------------------------------------------
#define QSTR 36   // float stride for q/k/v rows (16B aligned)
#define ASTR 53   // float stride for score matrix

__global__ __launch_bounds__(128) void attn_kernel(
    const float* __restrict__ qkv, const float* __restrict__ bm_tab,
    __nv_bfloat16* __restrict__ out_hi, __nv_bfloat16* __restrict__ out_lo)
{
    const int b = blockIdx.x;
    const int h = blockIdx.y;
    const int tid = threadIdx.x;

    __shared__ float q[52][QSTR];
    __shared__ float k[52][QSTR];
    __shared__ float v[52][QSTR];
    __shared__ float at[52][ASTR];

    // zero pad rows 49..51
    if (tid < 108) {
        int r = 49 + tid / QSTR, c = tid % QSTR;
        q[r][c] = 0.f; k[r][c] = 0.f; v[r][c] = 0.f;
    }

    const float scale = 0.17677669529663687f;  // 1/sqrt(32)
    const float* base = qkv + (long)b * SS * (3 * DIM) + h * HD;

    // load q/k/v: 49 rows x 3 mats x 8 float4
    for (int e = tid; e < SS * 24; e += 128) {
        int s = e / 24, rem = e % 24, r = rem >> 3, d4 = rem & 7;
        float4 val = *(const float4*)(base + (long)s * (3 * DIM) + r * DIM + d4 * 4);
        if (r == 0) {
            val.x *= scale; val.y *= scale; val.z *= scale; val.w *= scale;
            *(float4*)&q[s][d4 * 4] = val;
        } else if (r == 1) {
            *(float4*)&k[s][d4 * 4] = val;
        } else {
            *(float4*)&v[s][d4 * 4] = val;
        }
    }
    __syncthreads();

    // QK^T: 91 threads, each computes 4x7 scores with register tiling
    const float* bm = bm_tab + ((long)(b & 3) * HEADS + h) * (SS * SS);
    if (tid < 91) {
        const int qi0 = (tid / 7) * 4, ki0 = (tid % 7) * 7;
        float acc[4][7];
        #pragma unroll
        for (int i = 0; i < 4; i++)
            #pragma unroll
            for (int j = 0; j < 7; j++) acc[i][j] = 0.f;

        #pragma unroll
        for (int d0 = 0; d0 < HD; d0 += 4) {
            float4 q4[4], k4[7];
            #pragma unroll
            for (int i = 0; i < 4; i++) q4[i] = *(const float4*)&q[qi0 + i][d0];
            #pragma unroll
            for (int j = 0; j < 7; j++) k4[j] = *(const float4*)&k[ki0 + j][d0];
            #pragma unroll
            for (int i = 0; i < 4; i++)
                #pragma unroll
                for (int j = 0; j < 7; j++)
                    acc[i][j] += q4[i].x * k4[j].x + q4[i].y * k4[j].y +
                                 q4[i].z * k4[j].z + q4[i].w * k4[j].w;
        }
        #pragma unroll
        for (int i = 0; i < 4; i++) {
            const int qi = qi0 + i;
            #pragma unroll
            for (int j = 0; j < 7; j++) {
                const int ki = ki0 + j;
                at[qi][ki] = (qi < SS) ? acc[i][j] + bm[qi * SS + ki] : 0.f;
            }
        }
    }
    __syncthreads();

    // softmax: warp per row, shuffle reductions
    const int wid = tid >> 5, lane = tid & 31;
    for (int r = wid; r < SS; r += 4) {
        float v1 = at[r][lane];
        float v2 = (lane + 32 < SS) ? at[r][lane + 32] : -1e30f;
        float m = fmaxf(v1, v2);
        #pragma unroll
        for (int s = 16; s > 0; s >>= 1)
            m = fmaxf(m, __shfl_xor_sync(0xffffffff, m, s));
        float e1 = __expf(v1 - m);
        float e2 = (lane + 32 < SS) ? __expf(v2 - m) : 0.f;
        float sum = e1 + e2;
        #pragma unroll
        for (int s = 16; s > 0; s >>= 1)
            sum += __shfl_xor_sync(0xffffffff, sum, s);
        float inv = 1.0f / sum;
        at[r][lane] = e1 * inv;
        if (lane + 32 < SS) at[r][lane + 32] = e2 * inv;
    }
    __syncthreads();

    // AV: thread tile = 4 rows x 4 cols (float4); 13x8 = 104 active threads
    {
        const int qg = tid >> 3;
        if (qg < 13) {
            const int qi0 = qg * 4, d0 = (tid & 7) * 4;
            float4 a0 = {0,0,0,0}, a1 = {0,0,0,0}, a2 = {0,0,0,0}, a3 = {0,0,0,0};
            for (int j = 0; j < SS; j++) {
                float4 vv = *(const float4*)&v[j][d0];
                float p0 = at[qi0 + 0][j], p1 = at[qi0 + 1][j];
                float p2 = at[qi0 + 2][j], p3 = at[qi0 + 3][j];
                a0.x += p0 * vv.x; a0.y += p0 * vv.y; a0.z += p0 * vv.z; a0.w += p0 * vv.w;
                a1.x += p1 * vv.x; a1.y += p1 * vv.y; a1.z += p1 * vv.z; a1.w += p1 * vv.w;
                a2.x += p2 * vv.x; a2.y += p2 * vv.y; a2.z += p2 * vv.z; a2.w += p2 * vv.w;
                a3.x += p3 * vv.x; a3.y += p3 * vv.y; a3.z += p3 * vv.z; a3.w += p3 * vv.w;
            }
            float4 accs[4] = {a0, a1, a2, a3};
            #pragma unroll
            for (int i = 0; i < 4; i++) {
                const int qi = qi0 + i;
                if (qi < SS) {
                    const long idx = ((long)b * SS + qi) * DIM + h * HD + d0;
                    float4 s4 = accs[i];
                    __nv_bfloat16 h0 = __float2bfloat16(s4.x);
                    __nv_bfloat16 h1 = __float2bfloat16(s4.y);
                    __nv_bfloat16 h2 = __float2bfloat16(s4.z);
                    __nv_bfloat16 h3 = __float2bfloat16(s4.w);
                    __nv_bfloat162* hp = (__nv_bfloat162*)(out_hi + idx);
                    hp[0] = __nv_bfloat162(h0, h1);
                    hp[1] = __nv_bfloat162(h2, h3);
                    __nv_bfloat162* lp = (__nv_bfloat162*)(out_lo + idx);
                    lp[0] = __nv_bfloat162(
                        __float2bfloat16(s4.x - __bfloat162float(h0)),
                        __float2bfloat16(s4.y - __bfloat162float(h1)));
                    lp[1] = __nv_bfloat162(
                        __float2bfloat16(s4.z - __bfloat162float(h2)),
                        __float2bfloat16(s4.w - __bfloat162float(h3)));
                }
            }
        }
    }
}

// ---------------------------------------------------------------------------
extern "C" void kernel_launch(void* const* d_in, const int* in_sizes, int n_in,
                              void* d_out, int out_size)
{
    const float* x          = (const float*)d_in[0];
    const float* mask       = (const float*)d_in[1];
    const float* w_qkv      = (const float*)d_in[2];
    const float* b_qkv      = (const float*)d_in[3];
    const float* w_proj     = (const float*)d_in[4];
    const float* b_proj     = (const float*)d_in[5];
    const float* bias_table = (const float*)d_in[6];
    const int*   rel_idx    = (const int*)d_in[7];
    float* out = (float*)d_out;

    __nv_bfloat16 *xh, *xl, *ah, *al, *wqh, *wql, *wph, *wpl;
    float *qkv, *bm;
    cudaGetSymbolAddress((void**)&xh,  g_xh);
    cudaGetSymbolAddress((void**)&xl,  g_xl);
    cudaGetSymbolAddress((void**)&qkv, g_qkv);
    cudaGetSymbolAddress((void**)&ah,  g_ah);
    cudaGetSymbolAddress((void**)&al,  g_al);
    cudaGetSymbolAddress((void**)&wqh, g_wqh);
    cudaGetSymbolAddress((void**)&wql, g_wql);
    cudaGetSymbolAddress((void**)&wph, g_wph);
    cudaGetSymbolAddress((void**)&wpl, g_wpl);
    cudaGetSymbolAddress((void**)&bm,  g_bm);

    cudaFuncSetAttribute(gemm_bf16x3_mma,
                         cudaFuncAttributeMaxDynamicSharedMemorySize, GEMM_SMEM);

    // 1) splits + bias/mask table
    {
        long n4 = (long)MROWS * KDIM / 4;
        split_kernel<<<2048, 256>>>(x, xh, xl, n4);
        wsplit_kernel<<<(3 * DIM * KDIM) / 256, 256>>>(w_qkv, wqh, wql, 3 * DIM,
                                                       3 * DIM * KDIM);
        wsplit_kernel<<<(DIM * KDIM) / 256, 256>>>(w_proj, wph, wpl, DIM, DIM * KDIM);
        int bmtot = 4 * HEADS * SS * SS;
        biasmask_kernel<<<(bmtot + 255) / 256, 256>>>(bias_table, rel_idx, mask, bm);
    }

    // 2) QKV GEMM
    {
        dim3 grid(12, 784);
        gemm_bf16x3_mma<<<grid, 256, GEMM_SMEM>>>(xh, xl, wqh, wql, b_qkv, qkv,
                                                  3 * DIM);
    }

    // 3) window attention
    {
        dim3 grid(BTOT, HEADS);
        attn_kernel<<<grid, 128>>>(qkv, bm, ah, al);
    }

    // 4) Proj GEMM
    {
        dim3 grid(4, 784);
        gemm_bf16x3_mma<<<grid, 256, GEMM_SMEM>>>(ah, al, wph, wpl, b_proj, out,
                                                  DIM);
    }
}

// round 6
// speedup vs baseline: 2.5812x; 1.0738x over previous
#include <cuda_runtime.h>
#include <cuda_bf16.h>
#include <cstdint>

#define DIM   512
#define HEADS 16
#define HD    32
#define SS    49
#define BTOT  2048
#define MROWS (BTOT * SS)   // 100352 = 784 * 128
#define KDIM  512

// ---------------- scratch (__device__ globals; allocation-free rule) -------
__device__ __nv_bfloat16 g_xh[(size_t)MROWS * KDIM];
__device__ __nv_bfloat16 g_xl[(size_t)MROWS * KDIM];
__device__ float         g_qkv[(size_t)MROWS * 3 * DIM];
__device__ __nv_bfloat16 g_ah[(size_t)MROWS * DIM];
__device__ __nv_bfloat16 g_al[(size_t)MROWS * DIM];
__device__ __nv_bfloat16 g_wqh[(size_t)3 * DIM * KDIM];   // transposed [1536][512]
__device__ __nv_bfloat16 g_wql[(size_t)3 * DIM * KDIM];
__device__ __nv_bfloat16 g_wph[(size_t)DIM * KDIM];       // transposed [512][512]
__device__ __nv_bfloat16 g_wpl[(size_t)DIM * KDIM];
__device__ float         g_bm[4 * HEADS * SS * SS];       // bias+mask table

// ---------------- PTX helpers ---------------------------------------------
__device__ __forceinline__ uint32_t smem_u32(const void* p) {
    uint32_t a;
    asm("{ .reg .u64 t; cvta.to.shared.u64 t, %1; cvt.u32.u64 %0, t; }"
        : "=r"(a) : "l"(p));
    return a;
}
__device__ __forceinline__ void cpa16(uint32_t s, const void* g) {
    asm volatile("cp.async.cg.shared.global [%0], [%1], 16;" :: "r"(s), "l"(g));
}
#define CP_COMMIT() asm volatile("cp.async.commit_group;")
#define CP_WAIT1()  asm volatile("cp.async.wait_group 1;")

#define LDSM4(r, addr) \
    asm volatile("ldmatrix.sync.aligned.m8n8.x4.shared.b16 {%0,%1,%2,%3}, [%4];" \
        : "=r"((r)[0]), "=r"((r)[1]), "=r"((r)[2]), "=r"((r)[3]) : "r"(addr))

#define MMA16816(d, a, b0, b1) \
    asm volatile("mma.sync.aligned.m16n8k16.row.col.f32.bf16.bf16.f32 " \
        "{%0,%1,%2,%3}, {%4,%5,%6,%7}, {%8,%9}, {%0,%1,%2,%3};" \
        : "+f"((d)[0]), "+f"((d)[1]), "+f"((d)[2]), "+f"((d)[3]) \
        : "r"((a)[0]), "r"((a)[1]), "r"((a)[2]), "r"((a)[3]), "r"(b0), "r"(b1))

// ---------------------------------------------------------------------------
// Split-precision HMMA GEMM (unchanged from R5): C = (Ah+Al)@(Bh+Bl)^T + bias
// ---------------------------------------------------------------------------
#define TSTRIDE     80
#define TILE_BYTES  (128 * TSTRIDE)
#define STAGE_BYTES (4 * TILE_BYTES)
#define GEMM_SMEM   (2 * STAGE_BYTES)        // 81920

__global__ __launch_bounds__(256, 2) void gemm_bf16x3_mma(
    const __nv_bfloat16* __restrict__ Ah, const __nv_bfloat16* __restrict__ Al,
    const __nv_bfloat16* __restrict__ Bh, const __nv_bfloat16* __restrict__ Bl,
    const float* __restrict__ bias, float* __restrict__ C, int N)
{
    extern __shared__ char smem[];
    const uint32_t sb = smem_u32(smem);
    const int tid  = threadIdx.x;
    const int lane = tid & 31, wid = tid >> 5;
    const int wr = wid >> 2, wc = wid & 3;
    const long m0 = (long)blockIdx.y * 128;
    const int  n0 = blockIdx.x * 128;

    auto load_stage = [&](int s, int k0) {
        const uint32_t base = sb + (uint32_t)s * STAGE_BYTES;
        #pragma unroll
        for (int half = 0; half < 2; half++) {
            const int chunk = tid + half * 256;
            const int r = chunk >> 2, c = chunk & 3;
            const uint32_t off = (uint32_t)r * TSTRIDE + c * 16;
            const long aIdx = (m0 + r) * (long)KDIM + k0;
            const long bIdx = ((long)n0 + r) * (long)KDIM + k0;
            cpa16(base + off,                  (const char*)(Ah + aIdx) + c * 16);
            cpa16(base + TILE_BYTES + off,     (const char*)(Al + aIdx) + c * 16);
            cpa16(base + 2 * TILE_BYTES + off, (const char*)(Bh + bIdx) + c * 16);
            cpa16(base + 3 * TILE_BYTES + off, (const char*)(Bl + bIdx) + c * 16);
        }
    };

    float acc[4][4][4];
    #pragma unroll
    for (int mi = 0; mi < 4; mi++)
        #pragma unroll
        for (int ni = 0; ni < 4; ni++)
            #pragma unroll
            for (int j = 0; j < 4; j++) acc[mi][ni][j] = 0.f;

    const uint32_t aRowOff =
        (uint32_t)(wr * 64 + (lane & 15)) * TSTRIDE + (lane >> 4) * 16;
    const int bg = lane >> 3, bfr = bg >> 1, bkh = bg & 1;
    const uint32_t bRowOff0 =
        2 * TILE_BYTES + (uint32_t)(wc * 32 + bfr * 8 + (lane & 7)) * TSTRIDE + bkh * 16;

    auto compute_stage = [&](int s) {
        const uint32_t base = sb + (uint32_t)s * STAGE_BYTES;
        #pragma unroll
        for (int kk = 0; kk < 2; kk++) {
            uint32_t ah[4][4], al[4][4];
            #pragma unroll
            for (int mi = 0; mi < 4; mi++) {
                uint32_t addr = base + aRowOff + (uint32_t)mi * 16 * TSTRIDE + kk * 32;
                LDSM4(ah[mi], addr);
                LDSM4(al[mi], addr + TILE_BYTES);
            }
            #pragma unroll
            for (int p = 0; p < 2; p++) {
                uint32_t bh[4], bl[4];
                uint32_t addr = base + bRowOff0 + (uint32_t)p * 16 * TSTRIDE + kk * 32;
                LDSM4(bh, addr);
                LDSM4(bl, addr + TILE_BYTES);
                #pragma unroll
                for (int mi = 0; mi < 4; mi++)
                    #pragma unroll
                    for (int q2 = 0; q2 < 2; q2++) {
                        const int ni = p * 2 + q2, rb = q2 * 2;
                        MMA16816(acc[mi][ni], ah[mi], bh[rb], bh[rb + 1]);
                        MMA16816(acc[mi][ni], ah[mi], bl[rb], bl[rb + 1]);
                        MMA16816(acc[mi][ni], al[mi], bh[rb], bh[rb + 1]);
                    }
            }
        }
    };

    load_stage(0, 0);  CP_COMMIT();
    load_stage(1, 32); CP_COMMIT();
    #pragma unroll 1
    for (int kt = 0; kt < 16; kt++) {
        CP_WAIT1();
        __syncthreads();
        compute_stage(kt & 1);
        __syncthreads();
        if (kt + 2 < 16) {
            load_stage(kt & 1, (kt + 2) * 32);
            CP_COMMIT();
        }
    }

    const int r0 = lane >> 2, cpos = (lane & 3) * 2;
    #pragma unroll
    for (int ni = 0; ni < 4; ni++) {
        const int col = n0 + wc * 32 + ni * 8 + cpos;
        const float bx = bias[col], by = bias[col + 1];
        #pragma unroll
        for (int mi = 0; mi < 4; mi++) {
            const long row = m0 + wr * 64 + mi * 16 + r0;
            float2 v0 = {acc[mi][ni][0] + bx, acc[mi][ni][1] + by};
            float2 v1 = {acc[mi][ni][2] + bx, acc[mi][ni][3] + by};
            *(float2*)&C[row * (long)N + col]       = v0;
            *(float2*)&C[(row + 8) * (long)N + col] = v1;
        }
    }
}

// ---------------------------------------------------------------------------
// fp32 -> (hi, lo) bf16 split kernels
// ---------------------------------------------------------------------------
__global__ void split_kernel(const float* __restrict__ in,
                             __nv_bfloat16* __restrict__ hi,
                             __nv_bfloat16* __restrict__ lo, long n4)
{
    long i = (long)blockIdx.x * blockDim.x + threadIdx.x;
    const long stride = (long)gridDim.x * blockDim.x;
    for (; i < n4; i += stride) {
        float4 v = ((const float4*)in)[i];
        __nv_bfloat16 h0 = __float2bfloat16(v.x);
        __nv_bfloat16 h1 = __float2bfloat16(v.y);
        __nv_bfloat16 h2 = __float2bfloat16(v.z);
        __nv_bfloat16 h3 = __float2bfloat16(v.w);
        __nv_bfloat162* hp = (__nv_bfloat162*)hi + 2 * i;
        hp[0] = __nv_bfloat162(h0, h1);
        hp[1] = __nv_bfloat162(h2, h3);
        __nv_bfloat162* lp = (__nv_bfloat162*)lo + 2 * i;
        lp[0] = __nv_bfloat162(__float2bfloat16(v.x - __bfloat162float(h0)),
                               __float2bfloat16(v.y - __bfloat162float(h1)));
        lp[1] = __nv_bfloat162(__float2bfloat16(v.z - __bfloat162float(h2)),
                               __float2bfloat16(v.w - __bfloat162float(h3)));
    }
}

__global__ void wsplit_kernel(const float* __restrict__ w,
                              __nv_bfloat16* __restrict__ hi,
                              __nv_bfloat16* __restrict__ lo, int N, int total)
{
    int i = blockIdx.x * 256 + threadIdx.x;
    if (i >= total) return;
    int k = i & (KDIM - 1);
    int n = i >> 9;
    float v = w[(long)k * N + n];
    __nv_bfloat16 h = __float2bfloat16(v);
    hi[i] = h;
    lo[i] = __float2bfloat16(v - __bfloat162float(h));
}

__global__ void biasmask_kernel(const float* __restrict__ bias_table,
                                const int* __restrict__ rel_idx,
                                const float* __restrict__ mask,
                                float* __restrict__ bm)
{
    int idx = blockIdx.x * 256 + threadIdx.x;
    const int total = 4 * HEADS * SS * SS;
    if (idx >= total) return;
    int e = idx % (SS * SS);
    int h = (idx / (SS * SS)) % HEADS;
    int w = idx / (SS * SS * HEADS);
    bm[idx] = bias_table[rel_idx[e] * HEADS + h] + mask[w * SS * SS + e];
}

// ---------------------------------------------------------------------------
// MMA window attention. Block = (window, head), 128 threads / 4 warps.
// S padded 49->64. bf16x3 split for QK^T and P@V. Softmax on fragments.
// SMEM map (bytes): qh 0, ql 5120, kh 10240, kl 15360 (64x80 each)
//                   vth 20480, vtl 25088 (32x144 each, V transposed)
//                   ph 29696, pl 38912 (64x144 each)
//                   bm 48128 (64x68 f32 = 17408)   total 65536
// ---------------------------------------------------------------------------
#define AQH   0
#define AQL   5120
#define AKH   10240
#define AKL   15360
#define AVTH  20480
#define AVTL  25088
#define APH   29696
#define APL   38912
#define ABM   48128
#define ATTN_SMEM 65536

__global__ __launch_bounds__(128) void attn_mma_kernel(
    const float* __restrict__ qkv, const float* __restrict__ bm_tab,
    __nv_bfloat16* __restrict__ out_hi, __nv_bfloat16* __restrict__ out_lo)
{
    extern __shared__ char smem[];
    const uint32_t sb = smem_u32(smem);
    const int b = blockIdx.x, h = blockIdx.y;
    const int tid = threadIdx.x, lane = tid & 31, w = tid >> 5;

    // ---- zero pads: q/k rows 49..63 (4 tiles), whole Vt (2 tiles)
    for (int i = tid; i < 300; i += 128) {          // 15 rows * 20 words
        int r = 49 + i / 20, c = (i % 20) * 4;
        *(uint32_t*)(smem + AQH + r * 80 + c) = 0;
        *(uint32_t*)(smem + AQL + r * 80 + c) = 0;
        *(uint32_t*)(smem + AKH + r * 80 + c) = 0;
        *(uint32_t*)(smem + AKL + r * 80 + c) = 0;
    }
    for (int i = tid; i < 1152; i += 128) {         // 32*144/4
        *(uint32_t*)(smem + AVTH + i * 4) = 0;
        *(uint32_t*)(smem + AVTL + i * 4) = 0;
    }

    // ---- load + convert q,k,v
    const float scale = 0.17677669529663687f;
    const float* base = qkv + (long)b * SS * (3 * DIM) + h * HD;
    for (int e = tid; e < 392; e += 128) {          // 49 rows x 8 float4
        int s = e >> 3, d4 = (e & 7) * 4;
        const float* rp = base + (long)s * (3 * DIM) + d4;
        float4 qv = *(const float4*)rp;
        float4 kv = *(const float4*)(rp + DIM);
        float4 vv = *(const float4*)(rp + 2 * DIM);
        qv.x *= scale; qv.y *= scale; qv.z *= scale; qv.w *= scale;

        float qa[4] = {qv.x, qv.y, qv.z, qv.w};
        float ka[4] = {kv.x, kv.y, kv.z, kv.w};
        float va[4] = {vv.x, vv.y, vv.z, vv.w};
        __nv_bfloat16 qh_[4], ql_[4], kh_[4], kl_[4];
        #pragma unroll
        for (int j = 0; j < 4; j++) {
            qh_[j] = __float2bfloat16(qa[j]);
            ql_[j] = __float2bfloat16(qa[j] - __bfloat162float(qh_[j]));
            kh_[j] = __float2bfloat16(ka[j]);
            kl_[j] = __float2bfloat16(ka[j] - __bfloat162float(kh_[j]));
            __nv_bfloat16 vh = __float2bfloat16(va[j]);
            *(__nv_bfloat16*)(smem + AVTH + (d4 + j) * 144 + s * 2) = vh;
            *(__nv_bfloat16*)(smem + AVTL + (d4 + j) * 144 + s * 2) =
                __float2bfloat16(va[j] - __bfloat162float(vh));
        }
        uint32_t ro = (uint32_t)s * 80 + d4 * 2;
        *(__nv_bfloat162*)(smem + AQH + ro)     = __nv_bfloat162(qh_[0], qh_[1]);
        *(__nv_bfloat162*)(smem + AQH + ro + 4) = __nv_bfloat162(qh_[2], qh_[3]);
        *(__nv_bfloat162*)(smem + AQL + ro)     = __nv_bfloat162(ql_[0], ql_[1]);
        *(__nv_bfloat162*)(smem + AQL + ro + 4) = __nv_bfloat162(ql_[2], ql_[3]);
        *(__nv_bfloat162*)(smem + AKH + ro)     = __nv_bfloat162(kh_[0], kh_[1]);
        *(__nv_bfloat162*)(smem + AKH + ro + 4) = __nv_bfloat162(kh_[2], kh_[3]);
        *(__nv_bfloat162*)(smem + AKL + ro)     = __nv_bfloat162(kl_[0], kl_[1]);
        *(__nv_bfloat162*)(smem + AKL + ro + 4) = __nv_bfloat162(kl_[2], kl_[3]);
    }

    // ---- stage bias+mask with -1e30 padding
    const float* bm = bm_tab + ((long)(b & 3) * HEADS + h) * (SS * SS);
    for (int e = tid; e < 4096; e += 128) {
        int r = e >> 6, c = e & 63;
        float val = (r < SS && c < SS) ? bm[r * SS + c] : -1e30f;
        *(float*)(smem + ABM + r * 272 + c * 4) = val;
    }
    __syncthreads();

    // ---- QK^T: each warp 16 rows x 64 cols
    float accs[8][4];
    #pragma unroll
    for (int ni = 0; ni < 8; ni++)
        #pragma unroll
        for (int j = 0; j < 4; j++) accs[ni][j] = 0.f;

    const uint32_t aQ = sb + AQH +
        (uint32_t)(w * 16 + (lane & 15)) * 80 + (lane >> 4) * 16;
    const int bg = lane >> 3, bfr = bg >> 1, bkh = bg & 1;
    const uint32_t bK = sb + AKH +
        (uint32_t)(bfr * 8 + (lane & 7)) * 80 + bkh * 16;

    #pragma unroll
    for (int kk = 0; kk < 2; kk++) {
        uint32_t ah[4], al[4];
        LDSM4(ah, aQ + kk * 32);
        LDSM4(al, aQ + (AQL - AQH) + kk * 32);
        #pragma unroll
        for (int p = 0; p < 4; p++) {
            uint32_t bh[4], bl[4];
            uint32_t addr = bK + (uint32_t)p * 16 * 80 + kk * 32;
            LDSM4(bh, addr);
            LDSM4(bl, addr + (AKL - AKH));
            #pragma unroll
            for (int q2 = 0; q2 < 2; q2++) {
                const int ni = p * 2 + q2, rb = q2 * 2;
                MMA16816(accs[ni], ah, bh[rb], bh[rb + 1]);
                MMA16816(accs[ni], ah, bl[rb], bl[rb + 1]);
                MMA16816(accs[ni], al, bh[rb], bh[rb + 1]);
            }
        }
    }

    // ---- bias/mask add + softmax on fragments (rows r1, r1+8)
    const int r1 = lane >> 2, tq = lane & 3;
    const int row1 = w * 16 + r1, row2 = row1 + 8;
    {
        const float* bp1 = (const float*)(smem + ABM + row1 * 272);
        const float* bp2 = (const float*)(smem + ABM + row2 * 272);
        #pragma unroll
        for (int ni = 0; ni < 8; ni++) {
            int c0 = ni * 8 + tq * 2;
            accs[ni][0] += bp1[c0]; accs[ni][1] += bp1[c0 + 1];
            accs[ni][2] += bp2[c0]; accs[ni][3] += bp2[c0 + 1];
        }
        float m1 = -1e30f, m2 = -1e30f;
        #pragma unroll
        for (int ni = 0; ni < 8; ni++) {
            m1 = fmaxf(m1, fmaxf(accs[ni][0], accs[ni][1]));
            m2 = fmaxf(m2, fmaxf(accs[ni][2], accs[ni][3]));
        }
        m1 = fmaxf(m1, __shfl_xor_sync(0xffffffff, m1, 1));
        m1 = fmaxf(m1, __shfl_xor_sync(0xffffffff, m1, 2));
        m2 = fmaxf(m2, __shfl_xor_sync(0xffffffff, m2, 1));
        m2 = fmaxf(m2, __shfl_xor_sync(0xffffffff, m2, 2));
        float s1 = 0.f, s2 = 0.f;
        #pragma unroll
        for (int ni = 0; ni < 8; ni++) {
            accs[ni][0] = __expf(accs[ni][0] - m1);
            accs[ni][1] = __expf(accs[ni][1] - m1);
            accs[ni][2] = __expf(accs[ni][2] - m2);
            accs[ni][3] = __expf(accs[ni][3] - m2);
            s1 += accs[ni][0] + accs[ni][1];
            s2 += accs[ni][2] + accs[ni][3];
        }
        s1 += __shfl_xor_sync(0xffffffff, s1, 1);
        s1 += __shfl_xor_sync(0xffffffff, s1, 2);
        s2 += __shfl_xor_sync(0xffffffff, s2, 1);
        s2 += __shfl_xor_sync(0xffffffff, s2, 2);
        const float i1 = 1.0f / s1, i2 = 1.0f / s2;
        // split + store P to smem (A-layout, stride 144)
        #pragma unroll
        for (int ni = 0; ni < 8; ni++) {
            int co = (ni * 8 + tq * 2) * 2;
            float p0 = accs[ni][0] * i1, p1 = accs[ni][1] * i1;
            float p2 = accs[ni][2] * i2, p3 = accs[ni][3] * i2;
            __nv_bfloat16 h0 = __float2bfloat16(p0), h1 = __float2bfloat16(p1);
            __nv_bfloat16 h2 = __float2bfloat16(p2), h3 = __float2bfloat16(p3);
            *(__nv_bfloat162*)(smem + APH + row1 * 144 + co) = __nv_bfloat162(h0, h1);
            *(__nv_bfloat162*)(smem + APH + row2 * 144 + co) = __nv_bfloat162(h2, h3);
            *(__nv_bfloat162*)(smem + APL + row1 * 144 + co) = __nv_bfloat162(
                __float2bfloat16(p0 - __bfloat162float(h0)),
                __float2bfloat16(p1 - __bfloat162float(h1)));
            *(__nv_bfloat162*)(smem + APL + row2 * 144 + co) = __nv_bfloat162(
                __float2bfloat16(p2 - __bfloat162float(h2)),
                __float2bfloat16(p3 - __bfloat162float(h3)));
        }
    }
    __syncthreads();

    // ---- P @ V: M=64 (16/warp), N=32, K=64
    float acco[4][4];
    #pragma unroll
    for (int ni = 0; ni < 4; ni++)
        #pragma unroll
        for (int j = 0; j < 4; j++) acco[ni][j] = 0.f;

    const uint32_t aP = sb + APH +
        (uint32_t)(w * 16 + (lane & 15)) * 144 + (lane >> 4) * 16;
    const uint32_t bV = sb + AVTH +
        (uint32_t)(bfr * 8 + (lane & 7)) * 144 + bkh * 16;

    #pragma unroll
    for (int ks = 0; ks < 4; ks++) {
        uint32_t ph_[4], pl_[4];
        LDSM4(ph_, aP + ks * 32);
        LDSM4(pl_, aP + (APL - APH) + ks * 32);
        #pragma unroll
        for (int p = 0; p < 2; p++) {
            uint32_t bh[4], bl[4];
            uint32_t addr = bV + (uint32_t)p * 16 * 144 + ks * 32;
            LDSM4(bh, addr);
            LDSM4(bl, addr + (AVTL - AVTH));
            #pragma unroll
            for (int q2 = 0; q2 < 2; q2++) {
                const int ni = p * 2 + q2, rb = q2 * 2;
                MMA16816(acco[ni], ph_, bh[rb], bh[rb + 1]);
                MMA16816(acco[ni], ph_, bl[rb], bl[rb + 1]);
                MMA16816(acco[ni], pl_, bh[rb], bh[rb + 1]);
            }
        }
    }

    // ---- store split bf16 output
    #pragma unroll
    for (int ni = 0; ni < 4; ni++) {
        const int d0 = ni * 8 + tq * 2;
        if (row1 < SS) {
            long idx = ((long)b * SS + row1) * DIM + h * HD + d0;
            __nv_bfloat16 h0 = __float2bfloat16(acco[ni][0]);
            __nv_bfloat16 h1 = __float2bfloat16(acco[ni][1]);
            *(__nv_bfloat162*)(out_hi + idx) = __nv_bfloat162(h0, h1);
            *(__nv_bfloat162*)(out_lo + idx) = __nv_bfloat162(
                __float2bfloat16(acco[ni][0] - __bfloat162float(h0)),
                __float2bfloat16(acco[ni][1] - __bfloat162float(h1)));
        }
        if (row2 < SS) {
            long idx = ((long)b * SS + row2) * DIM + h * HD + d0;
            __nv_bfloat16 h2 = __float2bfloat16(acco[ni][2]);
            __nv_bfloat16 h3 = __float2bfloat16(acco[ni][3]);
            *(__nv_bfloat162*)(out_hi + idx) = __nv_bfloat162(h2, h3);
            *(__nv_bfloat162*)(out_lo + idx) = __nv_bfloat162(
                __float2bfloat16(acco[ni][2] - __bfloat162float(h2)),
                __float2bfloat16(acco[ni][3] - __bfloat162float(h3)));
        }
    }
}

// ---------------------------------------------------------------------------
extern "C" void kernel_launch(void* const* d_in, const int* in_sizes, int n_in,
                              void* d_out, int out_size)
{
    const float* x          = (const float*)d_in[0];
    const float* mask       = (const float*)d_in[1];
    const float* w_qkv      = (const float*)d_in[2];
    const float* b_qkv      = (const float*)d_in[3];
    const float* w_proj     = (const float*)d_in[4];
    const float* b_proj     = (const float*)d_in[5];
    const float* bias_table = (const float*)d_in[6];
    const int*   rel_idx    = (const int*)d_in[7];
    float* out = (float*)d_out;

    __nv_bfloat16 *xh, *xl, *ah, *al, *wqh, *wql, *wph, *wpl;
    float *qkv, *bm;
    cudaGetSymbolAddress((void**)&xh,  g_xh);
    cudaGetSymbolAddress((void**)&xl,  g_xl);
    cudaGetSymbolAddress((void**)&qkv, g_qkv);
    cudaGetSymbolAddress((void**)&ah,  g_ah);
    cudaGetSymbolAddress((void**)&al,  g_al);
    cudaGetSymbolAddress((void**)&wqh, g_wqh);
    cudaGetSymbolAddress((void**)&wql, g_wql);
    cudaGetSymbolAddress((void**)&wph, g_wph);
    cudaGetSymbolAddress((void**)&wpl, g_wpl);
    cudaGetSymbolAddress((void**)&bm,  g_bm);

    cudaFuncSetAttribute(gemm_bf16x3_mma,
                         cudaFuncAttributeMaxDynamicSharedMemorySize, GEMM_SMEM);
    cudaFuncSetAttribute(attn_mma_kernel,
                         cudaFuncAttributeMaxDynamicSharedMemorySize, ATTN_SMEM);

    // 1) splits + bias/mask table
    {
        long n4 = (long)MROWS * KDIM / 4;
        split_kernel<<<2048, 256>>>(x, xh, xl, n4);
        wsplit_kernel<<<(3 * DIM * KDIM) / 256, 256>>>(w_qkv, wqh, wql, 3 * DIM,
                                                       3 * DIM * KDIM);
        wsplit_kernel<<<(DIM * KDIM) / 256, 256>>>(w_proj, wph, wpl, DIM, DIM * KDIM);
        int bmtot = 4 * HEADS * SS * SS;
        biasmask_kernel<<<(bmtot + 255) / 256, 256>>>(bias_table, rel_idx, mask, bm);
    }

    // 2) QKV GEMM
    {
        dim3 grid(12, 784);
        gemm_bf16x3_mma<<<grid, 256, GEMM_SMEM>>>(xh, xl, wqh, wql, b_qkv, qkv,
                                                  3 * DIM);
    }

    // 3) MMA window attention
    {
        dim3 grid(BTOT, HEADS);
        attn_mma_kernel<<<grid, 128, ATTN_SMEM>>>(qkv, bm, ah, al);
    }

    // 4) Proj GEMM
    {
        dim3 grid(4, 784);
        gemm_bf16x3_mma<<<grid, 256, GEMM_SMEM>>>(ah, al, wph, wpl, b_proj, out,
                                                  DIM);
    }
}